// round 14
// baseline (speedup 1.0000x reference)
#include <cuda_runtime.h>
#include <cuda_bf16.h>
#include <math.h>
#include <stdint.h>
#include <cstdint>

// ---------------- problem constants ----------------
#define NLAYERS 6
#define BATCH   2
#define LSEQ    1024
#define DMODEL  512
#define EINNER  1024
#define NSTATE  16
#define RRANK   32
#define RBC     64            // RRANK + 2*NSTATE
#define TTOK    (BATCH*LSEQ)  // 2048
#define NCHUNK  64
#define TCH     (LSEQ/NCHUNK) // 16
#define EPSF    1.1920929e-07f
#define L2E     1.4426950408889634f

// weight plane layout (bf16 hi/lo), element offsets
#define N_IN   (NLAYERS*2*EINNER*DMODEL)
#define N_XP   (NLAYERS*RBC*EINNER)
#define N_DT   (NLAYERS*EINNER*RRANK)
#define N_OUT  (NLAYERS*DMODEL*EINNER)
#define OFF_IN  0
#define OFF_XP  (N_IN)
#define OFF_DT  (N_IN+N_XP)
#define OFF_OUT (N_IN+N_XP+N_DT)
#define N_WTOT  (N_IN+N_XP+N_DT+N_OUT)

// ---------------- scratch ----------------
__device__ float g_h   [TTOK*DMODEL];
__device__ float g_xz  [TTOK*2*EINNER];
__device__ float g_xi  [TTOK*EINNER];
__device__ float g_dbcp[8*TTOK*RBC];
__device__ float g_dbc [TTOK*RBC];
__device__ float g_dt  [TTOK*EINNER];
__device__ float g_ya  [TTOK*EINNER];
__device__ float g_cum [TTOK*EINNER];
__device__ float g_hN  [BATCH*NCHUNK*EINNER*NSTATE];
__device__ float g_P   [BATCH*NCHUNK*EINNER*NSTATE];
__device__ float g_S   [BATCH*NCHUNK*EINNER*NSTATE];
__device__ __nv_bfloat16 g_wh [N_WTOT], g_wl [N_WTOT];
__device__ __nv_bfloat16 g_xnh[TTOK*DMODEL],  g_xnl[TTOK*DMODEL];
__device__ __nv_bfloat16 g_xih[TTOK*EINNER],  g_xil[TTOK*EINNER];
__device__ __nv_bfloat16 g_dbch[TTOK*RBC],    g_dbcl[TTOK*RBC];
__device__ __nv_bfloat16 g_yh [TTOK*EINNER],  g_yl [TTOK*EINNER];

__device__ __forceinline__ void split_bf16(float v, __nv_bfloat16& h, __nv_bfloat16& l) {
    h = __float2bfloat16(v);
    l = __float2bfloat16(v - __bfloat162float(h));
}

__device__ __forceinline__ float fexp2n(float x) {
    x = fmaxf(x, -126.0f);
    float t = x + 12582912.0f;
    int   i = __float_as_int(t) - 0x4B400000;
    float r = x - (t - 12582912.0f);
    float p =          1.3333558e-3f;
    p = fmaf(p, r, 9.6181291e-3f);
    p = fmaf(p, r, 5.5504109e-2f);
    p = fmaf(p, r, 2.4022651e-1f);
    p = fmaf(p, r, 6.9314718e-1f);
    p = fmaf(p, r, 1.0f);
    return __int_as_float(__float_as_int(p) + (i << 23));
}

__device__ __forceinline__ float softplusf(float x) {
    return fmaxf(x, 0.0f) + log1pf(__expf(-fabsf(x)));
}

#define LDSM4(r0,r1,r2,r3,addr) \
    asm volatile("ldmatrix.sync.aligned.m8n8.x4.shared.b16 {%0,%1,%2,%3}, [%4];" \
        : "=r"(r0), "=r"(r1), "=r"(r2), "=r"(r3) : "r"(addr))

#define CP16(dst_u32, src_ptr) \
    asm volatile("cp.async.cg.shared.global [%0], [%1], 16;" :: "r"(dst_u32), "l"(src_ptr))
#define CP_COMMIT() asm volatile("cp.async.commit_group;" ::: "memory")
#define CP_WAIT0()  asm volatile("cp.async.wait_group 0;" ::: "memory")

// ---------------- K0: weights -> bf16 hi/lo planes ----------------
__global__ void k_cvtw(const float* __restrict__ inw, const float* __restrict__ xpw,
                       const float* __restrict__ dtw, const float* __restrict__ outw,
                       __nv_bfloat16* __restrict__ wh, __nv_bfloat16* __restrict__ wl) {
    int i4 = blockIdx.x * blockDim.x + threadIdx.x;
    int e0 = i4 * 4;
    if (e0 >= N_WTOT) return;
    const float* src; int off;
    if      (e0 < OFF_XP)  { src = inw;  off = e0 - OFF_IN;  }
    else if (e0 < OFF_DT)  { src = xpw;  off = e0 - OFF_XP;  }
    else if (e0 < OFF_OUT) { src = dtw;  off = e0 - OFF_DT;  }
    else                   { src = outw; off = e0 - OFF_OUT; }
    float4 v = *(const float4*)(src + off);
    __nv_bfloat16 h0,h1,h2,h3,l0,l1,l2,l3;
    split_bf16(v.x,h0,l0); split_bf16(v.y,h1,l1);
    split_bf16(v.z,h2,l2); split_bf16(v.w,h3,l3);
    *(__nv_bfloat162*)&wh[e0]   = __nv_bfloat162(h0,h1);
    *(__nv_bfloat162*)&wh[e0+2] = __nv_bfloat162(h2,h3);
    *(__nv_bfloat162*)&wl[e0]   = __nv_bfloat162(l0,l1);
    *(__nv_bfloat162*)&wl[e0+2] = __nv_bfloat162(l2,l3);
}

// ---------------- K1: h+pos then RMSNorm -> bf16 hi/lo ----------------
__global__ void k_addnorm(const float* __restrict__ hin, const float* __restrict__ pos,
                          const float* __restrict__ nw,
                          __nv_bfloat16* __restrict__ oh, __nv_bfloat16* __restrict__ ol) {
    int t = blockIdx.x;
    int tid = threadIdx.x;
    float4 v  = ((const float4*)(hin + t*DMODEL))[tid];
    float4 pv = ((const float4*)(pos + t*DMODEL))[tid];
    v.x += pv.x; v.y += pv.y; v.z += pv.z; v.w += pv.w;
    float ss = v.x*v.x + v.y*v.y + v.z*v.z + v.w*v.w;
    #pragma unroll
    for (int o = 16; o > 0; o >>= 1) ss += __shfl_xor_sync(0xffffffffu, ss, o);
    __shared__ float sred[4];
    if ((tid & 31) == 0) sred[tid >> 5] = ss;
    __syncthreads();
    ss = sred[0] + sred[1] + sred[2] + sred[3];
    float s = rsqrtf(ss * (1.0f/DMODEL) + EPSF);
    float4 w = ((const float4*)nw)[tid];
    float o0 = v.x*s*w.x, o1 = v.y*s*w.y, o2 = v.z*s*w.z, o3 = v.w*s*w.w;
    __nv_bfloat16 h0,h1,h2,h3,l0,l1,l2,l3;
    split_bf16(o0,h0,l0); split_bf16(o1,h1,l1);
    split_bf16(o2,h2,l2); split_bf16(o3,h3,l3);
    int base = t*DMODEL + tid*4;
    *(__nv_bfloat162*)&oh[base]   = __nv_bfloat162(h0,h1);
    *(__nv_bfloat162*)&oh[base+2] = __nv_bfloat162(h2,h3);
    *(__nv_bfloat162*)&ol[base]   = __nv_bfloat162(l0,l1);
    *(__nv_bfloat162*)&ol[base+2] = __nv_bfloat162(l2,l3);
}

// ---------------- bf16-split MMA GEMM: 64x64 tile, 256 thr (8 warps, 2x4), 2-stage ----
__device__ __forceinline__ void mma_bf16(float (&d)[4], const unsigned (&a)[4],
                                         const unsigned (&b)[2]) {
    asm volatile(
        "mma.sync.aligned.m16n8k16.row.col.f32.bf16.bf16.f32 "
        "{%0,%1,%2,%3}, {%4,%5,%6,%7}, {%8,%9}, {%0,%1,%2,%3};\n"
        : "+f"(d[0]), "+f"(d[1]), "+f"(d[2]), "+f"(d[3])
        : "r"(a[0]), "r"(a[1]), "r"(a[2]), "r"(a[3]), "r"(b[0]), "r"(b[1]));
}

template<int EPI>
__global__ void __launch_bounds__(256)
k_mma(const __nv_bfloat16* __restrict__ Agh, const __nv_bfloat16* __restrict__ Agl,
      const __nv_bfloat16* __restrict__ Bgh, const __nv_bfloat16* __restrict__ Bgl,
      float* __restrict__ C, int K, int lda, int ldw, int ldc,
      const float* __restrict__ bias, int pstride)
{
    constexpr int BM = 64, BK = 32;
    constexpr int TM = 2, TN = 2;               // warp tile 32x16, 8 warps (2x4)
    constexpr int LST = BK + 8;                 // 40 bf16 per smem row (80B)
    constexpr int BUFB = BM*LST*2;              // bytes per buffer per plane

    __shared__ __align__(16) __nv_bfloat16 Ah[2][BM*LST], Al[2][BM*LST];
    __shared__ __align__(16) __nv_bfloat16 Bh[2][BM*LST], Bl[2][BM*LST];

    const int tid  = threadIdx.x;
    const int lane = tid & 31;
    const int warp = tid >> 5;
    const int wm = (warp >> 2) * 32;            // 2 warps in M
    const int wn = (warp & 3) * 16;             // 4 warps in N
    const int m0 = blockIdx.y * BM, n0 = blockIdx.x * BM;
    const int kLen = K / gridDim.z;
    const int k0 = blockIdx.z * kLen;
    const int niter = kLen / BK;

    const int laneq = lane & 7;
    const int a_rowoff = (wm + laneq + ((lane>>3)&1)*8) * LST;
    const int a_koff   = (lane>>4)*8;
    const int b_rowoff = (wn + (lane>>4)*8 + laneq) * LST;
    const int b_koff   = ((lane>>3)&1)*8;

    const unsigned uAh = (unsigned)__cvta_generic_to_shared(&Ah[0][0]);
    const unsigned uAl = (unsigned)__cvta_generic_to_shared(&Al[0][0]);
    const unsigned uBh = (unsigned)__cvta_generic_to_shared(&Bh[0][0]);
    const unsigned uBl = (unsigned)__cvta_generic_to_shared(&Bl[0][0]);

    float acc[TM][TN][4];
    #pragma unroll
    for (int i = 0; i < TM; i++)
        #pragma unroll
        for (int j = 0; j < TN; j++)
            #pragma unroll
            for (int q = 0; q < 4; q++) acc[i][j][q] = 0.0f;

    // 256 threads cover all 256 uint4 positions of a 64x32 tile in one pass
    const int r_  = tid >> 2, kc_ = tid & 3;
    const int o0b = (r_*LST + kc_*8) * 2;

    auto issue_tile = [&](int buf, int kb) {
        const int bb = buf * BUFB;
        size_t gA = (size_t)(m0 + r_) * lda + kb + kc_*8;
        size_t gB = (size_t)(n0 + r_) * ldw + kb + kc_*8;
        CP16(uAh + bb + o0b, &Agh[gA]);
        CP16(uAl + bb + o0b, &Agl[gA]);
        CP16(uBh + bb + o0b, &Bgh[gB]);
        CP16(uBl + bb + o0b, &Bgl[gB]);
        CP_COMMIT();
    };

    issue_tile(0, k0);
    CP_WAIT0();
    __syncthreads();

    for (int kt = 0; kt < niter; kt++) {
        const int cur = kt & 1;
        const bool more = (kt + 1 < niter);
        if (more) issue_tile(cur ^ 1, k0 + (kt+1)*BK);

        const int bufB = cur * BUFB;
        #pragma unroll
        for (int s = 0; s < 2; s++) {
            unsigned bhf[TN][2], blf[TN][2];
            {
                int boff = bufB + (b_rowoff + s*16 + b_koff) * 2;
                unsigned t0,t1,t2,t3;
                LDSM4(t0,t1,t2,t3, uBh + boff);
                bhf[0][0]=t0; bhf[0][1]=t1; bhf[1][0]=t2; bhf[1][1]=t3;
                LDSM4(t0,t1,t2,t3, uBl + boff);
                blf[0][0]=t0; blf[0][1]=t1; blf[1][0]=t2; blf[1][1]=t3;
            }
            #pragma unroll
            for (int i = 0; i < TM; i++) {
                int aoff = bufB + (a_rowoff + i*16*LST + s*16 + a_koff) * 2;
                unsigned ahf[4], alf[4];
                LDSM4(ahf[0],ahf[1],ahf[2],ahf[3], uAh + aoff);
                LDSM4(alf[0],alf[1],alf[2],alf[3], uAl + aoff);
                #pragma unroll
                for (int j = 0; j < TN; j++) {
                    mma_bf16(acc[i][j], ahf, bhf[j]);
                    mma_bf16(acc[i][j], ahf, blf[j]);
                    mma_bf16(acc[i][j], alf, bhf[j]);
                }
            }
        }

        if (more) { CP_WAIT0(); }
        __syncthreads();
    }

    float* Cp = C + (size_t)blockIdx.z * pstride;
    #pragma unroll
    for (int i = 0; i < TM; i++) {
        int row = m0 + wm + i*16 + (lane >> 2);
        #pragma unroll
        for (int j = 0; j < TN; j++) {
            int col = n0 + wn + j*8 + (lane & 3)*2;
            float2 v0, v1;
            if (EPI == 1) {
                float b0 = bias[col], b1 = bias[col+1];
                v0.x = softplusf(acc[i][j][0] + b0);
                v0.y = softplusf(acc[i][j][1] + b1);
                v1.x = softplusf(acc[i][j][2] + b0);
                v1.y = softplusf(acc[i][j][3] + b1);
            } else {
                v0.x = acc[i][j][0]; v0.y = acc[i][j][1];
                v1.x = acc[i][j][2]; v1.y = acc[i][j][3];
            }
            *(float2*)&Cp[(size_t)row * ldc + col]     = v0;
            *(float2*)&Cp[(size_t)(row+8) * ldc + col] = v1;
        }
    }
}

// ---------------- K3: causal depthwise conv (k=4) + bias + SiLU ----------------
__global__ void k_conv(const float* __restrict__ xz, const float* __restrict__ cw,
                       const float* __restrict__ cb, float* __restrict__ xi,
                       __nv_bfloat16* __restrict__ xih, __nv_bfloat16* __restrict__ xil) {
    int idx = blockIdx.x * blockDim.x + threadIdx.x;
    int e  = idx & (EINNER - 1);
    int lg = (idx >> 10) & (LSEQ/4 - 1);
    int b  = idx >> 18;
    int l0 = lg * 4;
    const float* base = xz + (size_t)(b * LSEQ) * 2 * EINNER + e;
    float xv[7];
    #pragma unroll
    for (int j = 0; j < 7; j++) {
        int li = l0 - 3 + j;
        xv[j] = (li >= 0) ? base[(size_t)li * 2 * EINNER] : 0.0f;
    }
    float w0 = cw[e*4+0], w1 = cw[e*4+1], w2 = cw[e*4+2], w3 = cw[e*4+3];
    float bb = cb[e];
    #pragma unroll
    for (int t = 0; t < 4; t++) {
        float acc = bb;
        acc = fmaf(w0, xv[t+0], acc);
        acc = fmaf(w1, xv[t+1], acc);
        acc = fmaf(w2, xv[t+2], acc);
        acc = fmaf(w3, xv[t+3], acc);
        float v = acc / (1.0f + __expf(-acc));
        size_t oi = (size_t)(b*LSEQ + l0 + t) * EINNER + e;
        xi[oi] = v;
        __nv_bfloat16 h, lo; split_bf16(v, h, lo);
        xih[oi] = h; xil[oi] = lo;
    }
}

// ---------------- split-K reduce for x_proj (+ bf16 planes) ----------------
__global__ void k_reduce8(const float* __restrict__ part, float* __restrict__ out,
                          __nv_bfloat16* __restrict__ oh, __nv_bfloat16* __restrict__ ol,
                          int n) {
    int i = blockIdx.x * blockDim.x + threadIdx.x;
    if (i < n) {
        float s = 0.f;
        #pragma unroll
        for (int z = 0; z < 8; z++) s += part[(size_t)z * n + i];
        out[i] = s;
        __nv_bfloat16 h, lo; split_bf16(s, h, lo);
        oh[i] = h; ol[i] = lo;
    }
}

// ---------------- A setup helper ----------------
__device__ __forceinline__ bool load_A(const float* __restrict__ Alog, int e,
                                       float (&A2)[NSTATE]) {
    bool st = true;
    float A0 = -__expf(Alog[e*NSTATE]);
    #pragma unroll
    for (int n = 0; n < NSTATE; n++) {
        float An = -__expf(Alog[e*NSTATE + n]);
        A2[n] = An * L2E;
        st = st && (fabsf(An - (n+1)*A0) <= 1e-5f * fabsf(An));
    }
    return st;
}

// ---------------- scan pass 1 ----------------
__global__ void k_scan1(const float* __restrict__ dt, const float* __restrict__ u,
                        const float* __restrict__ dbc, const float* __restrict__ Alog,
                        float* __restrict__ hN, float* __restrict__ P,
                        float* __restrict__ yacc, float* __restrict__ cum) {
    int e = blockIdx.x * 128 + threadIdx.x;
    int c = blockIdx.y, b = blockIdx.z;
    int rowbase = b * LSEQ + c * TCH;
    __shared__ float sBC[TCH][2*NSTATE];
    for (int i = threadIdx.x; i < TCH*2*NSTATE; i += 128) {
        int r = i >> 5, n = i & 31;
        sBC[r][n] = dbc[(size_t)(rowbase + r) * RBC + RRANK + n];
    }
    float A2[NSTATE];
    bool st = load_A(Alog, e, A2);
    __syncthreads();

    float h[NSTATE];
    #pragma unroll
    for (int n = 0; n < NSTATE; n++) h[n] = 0.f;
    float cumd = 0.f;
    for (int tt = 0; tt < TCH; tt++) {
        int row = rowbase + tt;
        float d  = dt[(size_t)row * EINNER + e];
        float uu = u [(size_t)row * EINNER + e];
        float du = d * uu;
        float acc = 0.f;
        if (st) {
            float w = fexp2n(d * A2[0]);
            float a = 1.0f;
            #pragma unroll
            for (int n = 0; n < NSTATE; n++) {
                a *= w;
                h[n] = fmaf(a, h[n], du * sBC[tt][n]);
                acc = fmaf(h[n], sBC[tt][NSTATE + n], acc);
            }
        } else {
            #pragma unroll
            for (int n = 0; n < NSTATE; n++) {
                float a = fexp2n(d * A2[n]);
                h[n] = fmaf(a, h[n], du * sBC[tt][n]);
                acc = fmaf(h[n], sBC[tt][NSTATE + n], acc);
            }
        }
        cumd += d;
        size_t oi = (size_t)row * EINNER + e;
        yacc[oi] = acc;
        cum[oi]  = cumd;
    }
    int o = ((b * NCHUNK + c) * EINNER + e) * NSTATE;
    if (st) {
        float ws = fexp2n(cumd * A2[0]);
        float a = 1.0f;
        #pragma unroll
        for (int n = 0; n < NSTATE; n++) { a *= ws; hN[o+n] = h[n]; P[o+n] = a; }
    } else {
        #pragma unroll
        for (int n = 0; n < NSTATE; n++) { hN[o+n] = h[n]; P[o+n] = fexp2n(cumd * A2[n]); }
    }
}

// ---------------- scan pass 2 ----------------
__global__ void k_scan2(const float* __restrict__ hN, const float* __restrict__ P,
                        float* __restrict__ S) {
    int idx = blockIdx.x * blockDim.x + threadIdx.x;
    int b = idx >> 14;
    int r = idx & 16383;
    float s = 0.f;
    int base = b * NCHUNK * EINNER * NSTATE + r;
    #pragma unroll 8
    for (int c = 0; c < NCHUNK; c++) {
        S[base + c * EINNER * NSTATE] = s;
        s = hN[base + c * EINNER * NSTATE] + P[base + c * EINNER * NSTATE] * s;
    }
}

// ---------------- scan pass 3: parallel correction ----------------
__global__ void k_scan3(const float* __restrict__ u, const float* __restrict__ dbc,
                        const float* __restrict__ xz, const float* __restrict__ Alog,
                        const float* __restrict__ Dv, const float* __restrict__ S,
                        const float* __restrict__ yacc, const float* __restrict__ cum,
                        __nv_bfloat16* __restrict__ yh, __nv_bfloat16* __restrict__ yl) {
    int e = blockIdx.x * 128 + threadIdx.x;
    int c = blockIdx.y, b = blockIdx.z;
    int rowbase = b * LSEQ + c * TCH;
    __shared__ float sC[TCH][NSTATE];
    for (int i = threadIdx.x; i < TCH*NSTATE; i += 128) {
        int r = i >> 4, n = i & 15;
        sC[r][n] = dbc[(size_t)(rowbase + r) * RBC + RRANK + NSTATE + n];
    }
    float A2[NSTATE];
    bool st = load_A(Alog, e, A2);
    float Dd = Dv[e];
    float sreg[NSTATE];
    int o = ((b * NCHUNK + c) * EINNER + e) * NSTATE;
    #pragma unroll
    for (int n = 0; n < NSTATE; n++) sreg[n] = S[o + n];
    __syncthreads();

    for (int tt = 0; tt < TCH; tt++) {
        int row = rowbase + tt;
        size_t oi = (size_t)row * EINNER + e;
        float cd = cum[oi];
        float acc = yacc[oi];
        float uu  = u[oi];
        float zz  = xz[(size_t)row * 2 * EINNER + EINNER + e];
        if (st) {
            float wS = fexp2n(cd * A2[0]);
            float a = 1.0f;
            #pragma unroll
            for (int n = 0; n < NSTATE; n++) {
                a *= wS;
                acc = fmaf(a * sreg[n], sC[tt][n], acc);
            }
        } else {
            #pragma unroll
            for (int n = 0; n < NSTATE; n++)
                acc = fmaf(fexp2n(cd * A2[n]) * sreg[n], sC[tt][n], acc);
        }
        acc = fmaf(uu, Dd, acc);
        float sz = zz / (1.0f + __expf(-zz));
        float yv = acc * sz;
        __nv_bfloat16 hh, ll; split_bf16(yv, hh, ll);
        yh[oi] = hh; yl[oi] = ll;
    }
}

// ---------------- launcher: dual-stream overlap (fork/join from capture origin) ------
extern "C" void kernel_launch(void* const* d_in, const int* in_sizes, int n_in,
                              void* d_out, int out_size) {
    const float* x     = (const float*)d_in[0];
    const float* pos   = (const float*)d_in[1];
    const float* normw = (const float*)d_in[2];
    const float* inw   = (const float*)d_in[3];
    const float* convw = (const float*)d_in[4];
    const float* convb = (const float*)d_in[5];
    const float* xpw   = (const float*)d_in[6];
    const float* dtw   = (const float*)d_in[7];
    const float* dtb   = (const float*)d_in[8];
    const float* alog  = (const float*)d_in[9];
    const float* dvec  = (const float*)d_in[10];
    const float* outw  = (const float*)d_in[11];
    float* out = (float*)d_out;
    (void)in_sizes; (void)n_in; (void)out_size;

    static cudaStream_t s1, s2;
    static cudaEvent_t ev0, evJ, evA[NLAYERS], evB[NLAYERS];
    static int inited = 0;
    if (!inited) {
        cudaStreamCreateWithFlags(&s1, cudaStreamNonBlocking);
        cudaStreamCreateWithFlags(&s2, cudaStreamNonBlocking);
        cudaEventCreateWithFlags(&ev0, cudaEventDisableTiming);
        cudaEventCreateWithFlags(&evJ, cudaEventDisableTiming);
        for (int l = 0; l < NLAYERS; l++) {
            cudaEventCreateWithFlags(&evA[l], cudaEventDisableTiming);
            cudaEventCreateWithFlags(&evB[l], cudaEventDisableTiming);
        }
        inited = 1;
    }

    float *ph, *pxz, *pxi, *pdbcp, *pdbc, *pdt, *pya, *pcum, *phN, *pP, *pS;
    __nv_bfloat16 *pwh, *pwl, *pxnh, *pxnl, *pxih, *pxil, *pdbch, *pdbcl, *pyh, *pyl;
    cudaGetSymbolAddress((void**)&ph,    g_h);
    cudaGetSymbolAddress((void**)&pxz,   g_xz);
    cudaGetSymbolAddress((void**)&pxi,   g_xi);
    cudaGetSymbolAddress((void**)&pdbcp, g_dbcp);
    cudaGetSymbolAddress((void**)&pdbc,  g_dbc);
    cudaGetSymbolAddress((void**)&pdt,   g_dt);
    cudaGetSymbolAddress((void**)&pya,   g_ya);
    cudaGetSymbolAddress((void**)&pcum,  g_cum);
    cudaGetSymbolAddress((void**)&phN,   g_hN);
    cudaGetSymbolAddress((void**)&pP,    g_P);
    cudaGetSymbolAddress((void**)&pS,    g_S);
    cudaGetSymbolAddress((void**)&pwh,   g_wh);
    cudaGetSymbolAddress((void**)&pwl,   g_wl);
    cudaGetSymbolAddress((void**)&pxnh,  g_xnh);
    cudaGetSymbolAddress((void**)&pxnl,  g_xnl);
    cudaGetSymbolAddress((void**)&pxih,  g_xih);
    cudaGetSymbolAddress((void**)&pxil,  g_xil);
    cudaGetSymbolAddress((void**)&pdbch, g_dbch);
    cudaGetSymbolAddress((void**)&pdbcl, g_dbcl);
    cudaGetSymbolAddress((void**)&pyh,   g_yh);
    cudaGetSymbolAddress((void**)&pyl,   g_yl);

    // fork from the origin (default) stream
    cudaEventRecord(ev0, 0);
    cudaStreamWaitEvent(s1, ev0, 0);
    cudaStreamWaitEvent(s2, ev0, 0);

    k_cvtw<<<(N_WTOT/4 + 255)/256, 256, 0, s1>>>(inw, xpw, dtw, outw, pwh, pwl);

    for (int l = 0; l < NLAYERS; l++) {
        const float* hin = (l == 0) ? x : ph;
        // 1. h+pos -> rmsnorm -> xn planes (s1)
        k_addnorm<<<TTOK, 128, 0, s1>>>(hin, pos, normw, pxnh, pxnl);
        cudaEventRecord(evA[l], s1);
        cudaStreamWaitEvent(s2, evA[l], 0);
        // 2a. in_proj x-half on s1 (cols [0,EINNER)) -> feeds conv
        k_mma<0><<<dim3(EINNER/64, TTOK/64, 1), 256, 0, s1>>>(
            pxnh, pxnl, pwh + OFF_IN + (size_t)l*2*EINNER*DMODEL,
            pwl + OFF_IN + (size_t)l*2*EINNER*DMODEL, pxz,
            DMODEL, DMODEL, DMODEL, 2*EINNER, nullptr, 0);
        // 2b. in_proj z-half on s2 (cols [EINNER,2*EINNER)) -> needed only by scan3
        k_mma<0><<<dim3(EINNER/64, TTOK/64, 1), 256, 0, s2>>>(
            pxnh, pxnl, pwh + OFF_IN + (size_t)l*2*EINNER*DMODEL + (size_t)EINNER*DMODEL,
            pwl + OFF_IN + (size_t)l*2*EINNER*DMODEL + (size_t)EINNER*DMODEL, pxz + EINNER,
            DMODEL, DMODEL, DMODEL, 2*EINNER, nullptr, 0);
        cudaEventRecord(evB[l], s2);
        // 3. conv + SiLU (s1, depends on x-half only)
        k_conv<<<(TTOK*EINNER/4)/256, 256, 0, s1>>>(pxz, convw + (size_t)l*EINNER*4,
                                                    convb + (size_t)l*EINNER, pxi, pxih, pxil);
        // 4. x_proj split-K=8 + reduce -> dbc + planes (s1)
        k_mma<0><<<dim3(1, TTOK/64, 8), 256, 0, s1>>>(
            pxih, pxil, pwh + OFF_XP + (size_t)l*RBC*EINNER,
            pwl + OFF_XP + (size_t)l*RBC*EINNER, pdbcp,
            EINNER, EINNER, EINNER, RBC, nullptr, TTOK*RBC);
        k_reduce8<<<(TTOK*RBC)/256, 256, 0, s1>>>(pdbcp, pdbc, pdbch, pdbcl, TTOK*RBC);
        // 5. dt_proj + softplus (s1)
        k_mma<1><<<dim3(EINNER/64, TTOK/64, 1), 256, 0, s1>>>(
            pdbch, pdbcl, pwh + OFF_DT + (size_t)l*EINNER*RRANK,
            pwl + OFF_DT + (size_t)l*EINNER*RRANK, pdt,
            RRANK, RBC, RRANK, EINNER, dtb + (size_t)l*EINNER, 0);
        // 6. scan passes 1-2 (s1, no z dependency)
        k_scan1<<<dim3(EINNER/128, NCHUNK, BATCH), 128, 0, s1>>>(
            pdt, pxi, pdbc, alog + (size_t)l*EINNER*NSTATE, phN, pP, pya, pcum);
        k_scan2<<<(BATCH*EINNER*NSTATE)/256, 256, 0, s1>>>(phN, pP, pS);
        // join z-half before scan3 (gate needs z)
        cudaStreamWaitEvent(s1, evB[l], 0);
        k_scan3<<<dim3(EINNER/128, NCHUNK, BATCH), 128, 0, s1>>>(
            pxi, pdbc, pxz, alog + (size_t)l*EINNER*NSTATE,
            dvec + (size_t)l*EINNER, pS, pya, pcum, pyh, pyl);
        // 7. out_proj -> next h (or final output) (s1)
        float* dest = (l == NLAYERS-1) ? out : ph;
        k_mma<0><<<dim3(DMODEL/64, TTOK/64, 1), 256, 0, s1>>>(
            pyh, pyl, pwh + OFF_OUT + (size_t)l*DMODEL*EINNER,
            pwl + OFF_OUT + (size_t)l*DMODEL*EINNER, dest,
            EINNER, EINNER, EINNER, DMODEL, nullptr, 0);
    }

    // join back to origin stream
    cudaEventRecord(evJ, s1);
    cudaStreamWaitEvent(0, evJ, 0);
}

// round 15
// speedup vs baseline: 1.0384x; 1.0384x over previous
#include <cuda_runtime.h>
#include <cuda_bf16.h>
#include <math.h>
#include <stdint.h>
#include <cstdint>

// ---------------- problem constants ----------------
#define NLAYERS 6
#define BATCH   2
#define LSEQ    1024
#define DMODEL  512
#define EINNER  1024
#define NSTATE  16
#define RRANK   32
#define RBC     64            // RRANK + 2*NSTATE
#define TTOK    (BATCH*LSEQ)  // 2048
#define NCHUNK  64
#define TCH     (LSEQ/NCHUNK) // 16
#define EPSF    1.1920929e-07f
#define L2E     1.4426950408889634f

// weight plane layout (bf16 hi/lo), element offsets
#define LIN  (2*EINNER*DMODEL)
#define LXP  (RBC*EINNER)
#define LDT  (EINNER*RRANK)
#define LOUT (DMODEL*EINNER)
#define LTOT (LIN+LXP+LDT+LOUT)
#define N_IN   (NLAYERS*LIN)
#define N_XP   (NLAYERS*LXP)
#define N_DT   (NLAYERS*LDT)
#define N_OUT  (NLAYERS*LOUT)
#define OFF_IN  0
#define OFF_XP  (N_IN)
#define OFF_DT  (N_IN+N_XP)
#define OFF_OUT (N_IN+N_XP+N_DT)
#define N_WTOT  (N_IN+N_XP+N_DT+N_OUT)

// ---------------- scratch ----------------
__device__ float g_h   [TTOK*DMODEL];
__device__ float g_xz  [TTOK*2*EINNER];
__device__ float g_xi  [TTOK*EINNER];
__device__ float g_dbcp[8*TTOK*RBC];
__device__ float g_dbc [TTOK*RBC];
__device__ float g_dt  [TTOK*EINNER];
__device__ float g_ya  [TTOK*EINNER];
__device__ float g_cum [TTOK*EINNER];
__device__ float g_op  [2*TTOK*DMODEL];   // out_proj split-K partials
__device__ float g_hN  [BATCH*NCHUNK*EINNER*NSTATE];
__device__ float g_P   [BATCH*NCHUNK*EINNER*NSTATE];
__device__ float g_S   [BATCH*NCHUNK*EINNER*NSTATE];
__device__ __nv_bfloat16 g_wh [N_WTOT], g_wl [N_WTOT];
__device__ __nv_bfloat16 g_xnh[TTOK*DMODEL],  g_xnl[TTOK*DMODEL];
__device__ __nv_bfloat16 g_xih[TTOK*EINNER],  g_xil[TTOK*EINNER];
__device__ __nv_bfloat16 g_dbch[TTOK*RBC],    g_dbcl[TTOK*RBC];
__device__ __nv_bfloat16 g_yh [TTOK*EINNER],  g_yl [TTOK*EINNER];

__device__ __forceinline__ void split_bf16(float v, __nv_bfloat16& h, __nv_bfloat16& l) {
    h = __float2bfloat16(v);
    l = __float2bfloat16(v - __bfloat162float(h));
}

__device__ __forceinline__ float fexp2n(float x) {
    x = fmaxf(x, -126.0f);
    float t = x + 12582912.0f;
    int   i = __float_as_int(t) - 0x4B400000;
    float r = x - (t - 12582912.0f);
    float p =          1.3333558e-3f;
    p = fmaf(p, r, 9.6181291e-3f);
    p = fmaf(p, r, 5.5504109e-2f);
    p = fmaf(p, r, 2.4022651e-1f);
    p = fmaf(p, r, 6.9314718e-1f);
    p = fmaf(p, r, 1.0f);
    return __int_as_float(__float_as_int(p) + (i << 23));
}

__device__ __forceinline__ float softplusf(float x) {
    return fmaxf(x, 0.0f) + log1pf(__expf(-fabsf(x)));
}

#define LDSM4(r0,r1,r2,r3,addr) \
    asm volatile("ldmatrix.sync.aligned.m8n8.x4.shared.b16 {%0,%1,%2,%3}, [%4];" \
        : "=r"(r0), "=r"(r1), "=r"(r2), "=r"(r3) : "r"(addr))

#define CP16(dst_u32, src_ptr) \
    asm volatile("cp.async.cg.shared.global [%0], [%1], 16;" :: "r"(dst_u32), "l"(src_ptr))
#define CP_COMMIT() asm volatile("cp.async.commit_group;" ::: "memory")
#define CP_WAIT0()  asm volatile("cp.async.wait_group 0;" ::: "memory")

// ---------------- K0: per-layer weights -> bf16 hi/lo planes ----------------
__global__ void k_cvtw_layer(const float* __restrict__ inw, const float* __restrict__ xpw,
                             const float* __restrict__ dtw, const float* __restrict__ outw,
                             int l,
                             __nv_bfloat16* __restrict__ wh, __nv_bfloat16* __restrict__ wl) {
    int e0 = (blockIdx.x * blockDim.x + threadIdx.x) * 4;
    if (e0 >= LTOT) return;
    const float* src; size_t doff;
    if      (e0 < LIN)          { src = inw  + (size_t)l*LIN + e0;
                                  doff = OFF_IN  + (size_t)l*LIN + e0; }
    else if (e0 < LIN+LXP)      { src = xpw  + (size_t)l*LXP + (e0 - LIN);
                                  doff = OFF_XP  + (size_t)l*LXP + (e0 - LIN); }
    else if (e0 < LIN+LXP+LDT)  { src = dtw  + (size_t)l*LDT + (e0 - LIN - LXP);
                                  doff = OFF_DT  + (size_t)l*LDT + (e0 - LIN - LXP); }
    else                        { src = outw + (size_t)l*LOUT + (e0 - LIN - LXP - LDT);
                                  doff = OFF_OUT + (size_t)l*LOUT + (e0 - LIN - LXP - LDT); }
    float4 v = *(const float4*)src;
    __nv_bfloat16 h0,h1,h2,h3,l0,l1,l2,l3;
    split_bf16(v.x,h0,l0); split_bf16(v.y,h1,l1);
    split_bf16(v.z,h2,l2); split_bf16(v.w,h3,l3);
    *(__nv_bfloat162*)&wh[doff]   = __nv_bfloat162(h0,h1);
    *(__nv_bfloat162*)&wh[doff+2] = __nv_bfloat162(h2,h3);
    *(__nv_bfloat162*)&wl[doff]   = __nv_bfloat162(l0,l1);
    *(__nv_bfloat162*)&wl[doff+2] = __nv_bfloat162(l2,l3);
}

// ---------------- K1: h+pos then RMSNorm -> bf16 hi/lo ----------------
__global__ void k_addnorm(const float* __restrict__ hin, const float* __restrict__ pos,
                          const float* __restrict__ nw,
                          __nv_bfloat16* __restrict__ oh, __nv_bfloat16* __restrict__ ol) {
    int t = blockIdx.x;
    int tid = threadIdx.x;
    float4 v  = ((const float4*)(hin + t*DMODEL))[tid];
    float4 pv = ((const float4*)(pos + t*DMODEL))[tid];
    v.x += pv.x; v.y += pv.y; v.z += pv.z; v.w += pv.w;
    float ss = v.x*v.x + v.y*v.y + v.z*v.z + v.w*v.w;
    #pragma unroll
    for (int o = 16; o > 0; o >>= 1) ss += __shfl_xor_sync(0xffffffffu, ss, o);
    __shared__ float sred[4];
    if ((tid & 31) == 0) sred[tid >> 5] = ss;
    __syncthreads();
    ss = sred[0] + sred[1] + sred[2] + sred[3];
    float s = rsqrtf(ss * (1.0f/DMODEL) + EPSF);
    float4 w = ((const float4*)nw)[tid];
    float o0 = v.x*s*w.x, o1 = v.y*s*w.y, o2 = v.z*s*w.z, o3 = v.w*s*w.w;
    __nv_bfloat16 h0,h1,h2,h3,l0,l1,l2,l3;
    split_bf16(o0,h0,l0); split_bf16(o1,h1,l1);
    split_bf16(o2,h2,l2); split_bf16(o3,h3,l3);
    int base = t*DMODEL + tid*4;
    *(__nv_bfloat162*)&oh[base]   = __nv_bfloat162(h0,h1);
    *(__nv_bfloat162*)&oh[base+2] = __nv_bfloat162(h2,h3);
    *(__nv_bfloat162*)&ol[base]   = __nv_bfloat162(l0,l1);
    *(__nv_bfloat162*)&ol[base+2] = __nv_bfloat162(l2,l3);
}

// ---------------- bf16-split MMA GEMM (R13 proven: 64x64, 128 thr, 2-stage) ----------
__device__ __forceinline__ void mma_bf16(float (&d)[4], const unsigned (&a)[4],
                                         const unsigned (&b)[2]) {
    asm volatile(
        "mma.sync.aligned.m16n8k16.row.col.f32.bf16.bf16.f32 "
        "{%0,%1,%2,%3}, {%4,%5,%6,%7}, {%8,%9}, {%0,%1,%2,%3};\n"
        : "+f"(d[0]), "+f"(d[1]), "+f"(d[2]), "+f"(d[3])
        : "r"(a[0]), "r"(a[1]), "r"(a[2]), "r"(a[3]), "r"(b[0]), "r"(b[1]));
}

template<int EPI>
__global__ void __launch_bounds__(128)
k_mma(const __nv_bfloat16* __restrict__ Agh, const __nv_bfloat16* __restrict__ Agl,
      const __nv_bfloat16* __restrict__ Bgh, const __nv_bfloat16* __restrict__ Bgl,
      float* __restrict__ C, int K, int lda, int ldw, int ldc,
      const float* __restrict__ bias, int pstride)
{
    constexpr int BM = 64, BK = 32, THREADS = 128;
    constexpr int TM = 2, TN = 4;
    constexpr int LST = BK + 8;
    constexpr int BUFB = BM*LST*2;

    __shared__ __align__(16) __nv_bfloat16 Ah[2][BM*LST], Al[2][BM*LST];
    __shared__ __align__(16) __nv_bfloat16 Bh[2][BM*LST], Bl[2][BM*LST];

    const int tid  = threadIdx.x;
    const int lane = tid & 31;
    const int warp = tid >> 5;
    const int wm = (warp >> 1) * 32;
    const int wn = (warp & 1) * 32;
    const int m0 = blockIdx.y * BM, n0 = blockIdx.x * BM;
    const int kLen = K / gridDim.z;
    const int k0 = blockIdx.z * kLen;
    const int niter = kLen / BK;

    const int laneq = lane & 7;
    const int a_rowoff = (wm + laneq + ((lane>>3)&1)*8) * LST;
    const int a_koff   = (lane>>4)*8;
    const int b_rowoff = (wn + (lane>>4)*8 + laneq) * LST;
    const int b_koff   = ((lane>>3)&1)*8;

    const unsigned uAh = (unsigned)__cvta_generic_to_shared(&Ah[0][0]);
    const unsigned uAl = (unsigned)__cvta_generic_to_shared(&Al[0][0]);
    const unsigned uBh = (unsigned)__cvta_generic_to_shared(&Bh[0][0]);
    const unsigned uBl = (unsigned)__cvta_generic_to_shared(&Bl[0][0]);

    float acc[TM][TN][4];
    #pragma unroll
    for (int i = 0; i < TM; i++)
        #pragma unroll
        for (int j = 0; j < TN; j++)
            #pragma unroll
            for (int q = 0; q < 4; q++) acc[i][j][q] = 0.0f;

    const int r_  = tid >> 2,             kc_  = tid & 3;
    const int r2_ = (tid + THREADS) >> 2, kc2_ = (tid + THREADS) & 3;
    const int o0b = (r_*LST + kc_*8) * 2, o1b = (r2_*LST + kc2_*8) * 2;

    auto issue_tile = [&](int buf, int kb) {
        const int bb = buf * BUFB;
        size_t gA0 = (size_t)(m0 + r_ ) * lda + kb + kc_ *8;
        size_t gA1 = (size_t)(m0 + r2_) * lda + kb + kc2_*8;
        size_t gB0 = (size_t)(n0 + r_ ) * ldw + kb + kc_ *8;
        size_t gB1 = (size_t)(n0 + r2_) * ldw + kb + kc2_*8;
        CP16(uAh + bb + o0b, &Agh[gA0]);
        CP16(uAl + bb + o0b, &Agl[gA0]);
        CP16(uAh + bb + o1b, &Agh[gA1]);
        CP16(uAl + bb + o1b, &Agl[gA1]);
        CP16(uBh + bb + o0b, &Bgh[gB0]);
        CP16(uBl + bb + o0b, &Bgl[gB0]);
        CP16(uBh + bb + o1b, &Bgh[gB1]);
        CP16(uBl + bb + o1b, &Bgl[gB1]);
        CP_COMMIT();
    };

    issue_tile(0, k0);
    CP_WAIT0();
    __syncthreads();

    for (int kt = 0; kt < niter; kt++) {
        const int cur = kt & 1;
        const bool more = (kt + 1 < niter);
        if (more) issue_tile(cur ^ 1, k0 + (kt+1)*BK);

        const int bufB = cur * BUFB;
        #pragma unroll
        for (int s = 0; s < 2; s++) {
            unsigned bhf[TN][2], blf[TN][2];
            {
                int boff = bufB + (b_rowoff + s*16 + b_koff) * 2;
                unsigned t0,t1,t2,t3;
                LDSM4(t0,t1,t2,t3, uBh + boff);
                bhf[0][0]=t0; bhf[0][1]=t1; bhf[1][0]=t2; bhf[1][1]=t3;
                LDSM4(t0,t1,t2,t3, uBh + boff + 16*LST*2);
                bhf[2][0]=t0; bhf[2][1]=t1; bhf[3][0]=t2; bhf[3][1]=t3;
                LDSM4(t0,t1,t2,t3, uBl + boff);
                blf[0][0]=t0; blf[0][1]=t1; blf[1][0]=t2; blf[1][1]=t3;
                LDSM4(t0,t1,t2,t3, uBl + boff + 16*LST*2);
                blf[2][0]=t0; blf[2][1]=t1; blf[3][0]=t2; blf[3][1]=t3;
            }
            #pragma unroll
            for (int i = 0; i < TM; i++) {
                int aoff = bufB + (a_rowoff + i*16*LST + s*16 + a_koff) * 2;
                unsigned ahf[4], alf[4];
                LDSM4(ahf[0],ahf[1],ahf[2],ahf[3], uAh + aoff);
                LDSM4(alf[0],alf[1],alf[2],alf[3], uAl + aoff);
                #pragma unroll
                for (int j = 0; j < TN; j++) {
                    mma_bf16(acc[i][j], ahf, bhf[j]);
                    mma_bf16(acc[i][j], ahf, blf[j]);
                    mma_bf16(acc[i][j], alf, bhf[j]);
                }
            }
        }

        if (more) { CP_WAIT0(); }
        __syncthreads();
    }

    float* Cp = C + (size_t)blockIdx.z * pstride;
    #pragma unroll
    for (int i = 0; i < TM; i++) {
        int row = m0 + wm + i*16 + (lane >> 2);
        #pragma unroll
        for (int j = 0; j < TN; j++) {
            int col = n0 + wn + j*8 + (lane & 3)*2;
            float2 v0, v1;
            if (EPI == 1) {
                float b0 = bias[col], b1 = bias[col+1];
                v0.x = softplusf(acc[i][j][0] + b0);
                v0.y = softplusf(acc[i][j][1] + b1);
                v1.x = softplusf(acc[i][j][2] + b0);
                v1.y = softplusf(acc[i][j][3] + b1);
            } else {
                v0.x = acc[i][j][0]; v0.y = acc[i][j][1];
                v1.x = acc[i][j][2]; v1.y = acc[i][j][3];
            }
            *(float2*)&Cp[(size_t)row * ldc + col]     = v0;
            *(float2*)&Cp[(size_t)(row+8) * ldc + col] = v1;
        }
    }
}

// ---------------- K3: causal depthwise conv (k=4) + bias + SiLU ----------------
__global__ void k_conv(const float* __restrict__ xz, const float* __restrict__ cw,
                       const float* __restrict__ cb, float* __restrict__ xi,
                       __nv_bfloat16* __restrict__ xih, __nv_bfloat16* __restrict__ xil) {
    int idx = blockIdx.x * blockDim.x + threadIdx.x;
    int e  = idx & (EINNER - 1);
    int lg = (idx >> 10) & (LSEQ/4 - 1);
    int b  = idx >> 18;
    int l0 = lg * 4;
    const float* base = xz + (size_t)(b * LSEQ) * 2 * EINNER + e;
    float xv[7];
    #pragma unroll
    for (int j = 0; j < 7; j++) {
        int li = l0 - 3 + j;
        xv[j] = (li >= 0) ? base[(size_t)li * 2 * EINNER] : 0.0f;
    }
    float w0 = cw[e*4+0], w1 = cw[e*4+1], w2 = cw[e*4+2], w3 = cw[e*4+3];
    float bb = cb[e];
    #pragma unroll
    for (int t = 0; t < 4; t++) {
        float acc = bb;
        acc = fmaf(w0, xv[t+0], acc);
        acc = fmaf(w1, xv[t+1], acc);
        acc = fmaf(w2, xv[t+2], acc);
        acc = fmaf(w3, xv[t+3], acc);
        float v = acc / (1.0f + __expf(-acc));
        size_t oi = (size_t)(b*LSEQ + l0 + t) * EINNER + e;
        xi[oi] = v;
        __nv_bfloat16 h, lo; split_bf16(v, h, lo);
        xih[oi] = h; xil[oi] = lo;
    }
}

// ---------------- split-K reduce for x_proj (+ bf16 planes) ----------------
__global__ void k_reduce8(const float* __restrict__ part, float* __restrict__ out,
                          __nv_bfloat16* __restrict__ oh, __nv_bfloat16* __restrict__ ol,
                          int n) {
    int i = blockIdx.x * blockDim.x + threadIdx.x;
    if (i < n) {
        float s = 0.f;
        #pragma unroll
        for (int z = 0; z < 8; z++) s += part[(size_t)z * n + i];
        out[i] = s;
        __nv_bfloat16 h, lo; split_bf16(s, h, lo);
        oh[i] = h; ol[i] = lo;
    }
}

// ---------------- split-K=2 reduce for out_proj ----------------
__global__ void k_reduce2(const float* __restrict__ part, float* __restrict__ out, int n4) {
    int i = blockIdx.x * blockDim.x + threadIdx.x;
    if (i < n4) {
        float4 a = ((const float4*)part)[i];
        float4 b = ((const float4*)(part + (size_t)n4*4))[i];
        a.x += b.x; a.y += b.y; a.z += b.z; a.w += b.w;
        ((float4*)out)[i] = a;
    }
}

// ---------------- A setup helper ----------------
__device__ __forceinline__ bool load_A(const float* __restrict__ Alog, int e,
                                       float (&A2)[NSTATE]) {
    bool st = true;
    float A0 = -__expf(Alog[e*NSTATE]);
    #pragma unroll
    for (int n = 0; n < NSTATE; n++) {
        float An = -__expf(Alog[e*NSTATE + n]);
        A2[n] = An * L2E;
        st = st && (fabsf(An - (n+1)*A0) <= 1e-5f * fabsf(An));
    }
    return st;
}

// ---------------- scan pass 1 ----------------
__global__ void k_scan1(const float* __restrict__ dt, const float* __restrict__ u,
                        const float* __restrict__ dbc, const float* __restrict__ Alog,
                        float* __restrict__ hN, float* __restrict__ P,
                        float* __restrict__ yacc, float* __restrict__ cum) {
    int e = blockIdx.x * 128 + threadIdx.x;
    int c = blockIdx.y, b = blockIdx.z;
    int rowbase = b * LSEQ + c * TCH;
    __shared__ float sBC[TCH][2*NSTATE];
    for (int i = threadIdx.x; i < TCH*2*NSTATE; i += 128) {
        int r = i >> 5, n = i & 31;
        sBC[r][n] = dbc[(size_t)(rowbase + r) * RBC + RRANK + n];
    }
    float A2[NSTATE];
    bool st = load_A(Alog, e, A2);
    __syncthreads();

    float h[NSTATE];
    #pragma unroll
    for (int n = 0; n < NSTATE; n++) h[n] = 0.f;
    float cumd = 0.f;
    for (int tt = 0; tt < TCH; tt++) {
        int row = rowbase + tt;
        float d  = dt[(size_t)row * EINNER + e];
        float uu = u [(size_t)row * EINNER + e];
        float du = d * uu;
        float acc = 0.f;
        if (st) {
            float w = fexp2n(d * A2[0]);
            float a = 1.0f;
            #pragma unroll
            for (int n = 0; n < NSTATE; n++) {
                a *= w;
                h[n] = fmaf(a, h[n], du * sBC[tt][n]);
                acc = fmaf(h[n], sBC[tt][NSTATE + n], acc);
            }
        } else {
            #pragma unroll
            for (int n = 0; n < NSTATE; n++) {
                float a = fexp2n(d * A2[n]);
                h[n] = fmaf(a, h[n], du * sBC[tt][n]);
                acc = fmaf(h[n], sBC[tt][NSTATE + n], acc);
            }
        }
        cumd += d;
        size_t oi = (size_t)row * EINNER + e;
        yacc[oi] = acc;
        cum[oi]  = cumd;
    }
    int o = ((b * NCHUNK + c) * EINNER + e) * NSTATE;
    if (st) {
        float ws = fexp2n(cumd * A2[0]);
        float a = 1.0f;
        #pragma unroll
        for (int n = 0; n < NSTATE; n++) { a *= ws; hN[o+n] = h[n]; P[o+n] = a; }
    } else {
        #pragma unroll
        for (int n = 0; n < NSTATE; n++) { hN[o+n] = h[n]; P[o+n] = fexp2n(cumd * A2[n]); }
    }
}

// ---------------- scan pass 2 ----------------
__global__ void k_scan2(const float* __restrict__ hN, const float* __restrict__ P,
                        float* __restrict__ S) {
    int idx = blockIdx.x * blockDim.x + threadIdx.x;
    int b = idx >> 14;
    int r = idx & 16383;
    float s = 0.f;
    int base = b * NCHUNK * EINNER * NSTATE + r;
    #pragma unroll 8
    for (int c = 0; c < NCHUNK; c++) {
        S[base + c * EINNER * NSTATE] = s;
        s = hN[base + c * EINNER * NSTATE] + P[base + c * EINNER * NSTATE] * s;
    }
}

// ---------------- scan pass 3: parallel correction ----------------
__global__ void k_scan3(const float* __restrict__ u, const float* __restrict__ dbc,
                        const float* __restrict__ xz, const float* __restrict__ Alog,
                        const float* __restrict__ Dv, const float* __restrict__ S,
                        const float* __restrict__ yacc, const float* __restrict__ cum,
                        __nv_bfloat16* __restrict__ yh, __nv_bfloat16* __restrict__ yl) {
    int e = blockIdx.x * 128 + threadIdx.x;
    int c = blockIdx.y, b = blockIdx.z;
    int rowbase = b * LSEQ + c * TCH;
    __shared__ float sC[TCH][NSTATE];
    for (int i = threadIdx.x; i < TCH*NSTATE; i += 128) {
        int r = i >> 4, n = i & 15;
        sC[r][n] = dbc[(size_t)(rowbase + r) * RBC + RRANK + NSTATE + n];
    }
    float A2[NSTATE];
    bool st = load_A(Alog, e, A2);
    float Dd = Dv[e];
    float sreg[NSTATE];
    int o = ((b * NCHUNK + c) * EINNER + e) * NSTATE;
    #pragma unroll
    for (int n = 0; n < NSTATE; n++) sreg[n] = S[o + n];
    __syncthreads();

    for (int tt = 0; tt < TCH; tt++) {
        int row = rowbase + tt;
        size_t oi = (size_t)row * EINNER + e;
        float cd = cum[oi];
        float acc = yacc[oi];
        float uu  = u[oi];
        float zz  = xz[(size_t)row * 2 * EINNER + EINNER + e];
        if (st) {
            float wS = fexp2n(cd * A2[0]);
            float a = 1.0f;
            #pragma unroll
            for (int n = 0; n < NSTATE; n++) {
                a *= wS;
                acc = fmaf(a * sreg[n], sC[tt][n], acc);
            }
        } else {
            #pragma unroll
            for (int n = 0; n < NSTATE; n++)
                acc = fmaf(fexp2n(cd * A2[n]) * sreg[n], sC[tt][n], acc);
        }
        acc = fmaf(uu, Dd, acc);
        float sz = zz / (1.0f + __expf(-zz));
        float yv = acc * sz;
        __nv_bfloat16 hh, ll; split_bf16(yv, hh, ll);
        yh[oi] = hh; yl[oi] = ll;
    }
}

// ---------------- launcher: dual-stream overlap + lazy weight conversion ------
extern "C" void kernel_launch(void* const* d_in, const int* in_sizes, int n_in,
                              void* d_out, int out_size) {
    const float* x     = (const float*)d_in[0];
    const float* pos   = (const float*)d_in[1];
    const float* normw = (const float*)d_in[2];
    const float* inw   = (const float*)d_in[3];
    const float* convw = (const float*)d_in[4];
    const float* convb = (const float*)d_in[5];
    const float* xpw   = (const float*)d_in[6];
    const float* dtw   = (const float*)d_in[7];
    const float* dtb   = (const float*)d_in[8];
    const float* alog  = (const float*)d_in[9];
    const float* dvec  = (const float*)d_in[10];
    const float* outw  = (const float*)d_in[11];
    float* out = (float*)d_out;
    (void)in_sizes; (void)n_in; (void)out_size;

    static cudaStream_t s1, s2;
    static cudaEvent_t ev0, evJ, evA[NLAYERS], evB[NLAYERS], evC[NLAYERS];
    static int inited = 0;
    if (!inited) {
        cudaStreamCreateWithFlags(&s1, cudaStreamNonBlocking);
        cudaStreamCreateWithFlags(&s2, cudaStreamNonBlocking);
        cudaEventCreateWithFlags(&ev0, cudaEventDisableTiming);
        cudaEventCreateWithFlags(&evJ, cudaEventDisableTiming);
        for (int l = 0; l < NLAYERS; l++) {
            cudaEventCreateWithFlags(&evA[l], cudaEventDisableTiming);
            cudaEventCreateWithFlags(&evB[l], cudaEventDisableTiming);
            cudaEventCreateWithFlags(&evC[l], cudaEventDisableTiming);
        }
        inited = 1;
    }

    float *ph, *pxz, *pxi, *pdbcp, *pdbc, *pdt, *pya, *pcum, *pop, *phN, *pP, *pS;
    __nv_bfloat16 *pwh, *pwl, *pxnh, *pxnl, *pxih, *pxil, *pdbch, *pdbcl, *pyh, *pyl;
    cudaGetSymbolAddress((void**)&ph,    g_h);
    cudaGetSymbolAddress((void**)&pxz,   g_xz);
    cudaGetSymbolAddress((void**)&pxi,   g_xi);
    cudaGetSymbolAddress((void**)&pdbcp, g_dbcp);
    cudaGetSymbolAddress((void**)&pdbc,  g_dbc);
    cudaGetSymbolAddress((void**)&pdt,   g_dt);
    cudaGetSymbolAddress((void**)&pya,   g_ya);
    cudaGetSymbolAddress((void**)&pcum,  g_cum);
    cudaGetSymbolAddress((void**)&pop,   g_op);
    cudaGetSymbolAddress((void**)&phN,   g_hN);
    cudaGetSymbolAddress((void**)&pP,    g_P);
    cudaGetSymbolAddress((void**)&pS,    g_S);
    cudaGetSymbolAddress((void**)&pwh,   g_wh);
    cudaGetSymbolAddress((void**)&pwl,   g_wl);
    cudaGetSymbolAddress((void**)&pxnh,  g_xnh);
    cudaGetSymbolAddress((void**)&pxnl,  g_xnl);
    cudaGetSymbolAddress((void**)&pxih,  g_xih);
    cudaGetSymbolAddress((void**)&pxil,  g_xil);
    cudaGetSymbolAddress((void**)&pdbch, g_dbch);
    cudaGetSymbolAddress((void**)&pdbcl, g_dbcl);
    cudaGetSymbolAddress((void**)&pyh,   g_yh);
    cudaGetSymbolAddress((void**)&pyl,   g_yl);

    const int CVT_BLOCKS = (LTOT/4 + 255) / 256;

    // fork from the origin (default) stream
    cudaEventRecord(ev0, 0);
    cudaStreamWaitEvent(s1, ev0, 0);
    cudaStreamWaitEvent(s2, ev0, 0);

    // layer 0 weights converted up-front on s1
    k_cvtw_layer<<<CVT_BLOCKS, 256, 0, s1>>>(inw, xpw, dtw, outw, 0, pwh, pwl);

    for (int l = 0; l < NLAYERS; l++) {
        const float* hin = (l == 0) ? x : ph;
        // 1. h+pos -> rmsnorm -> xn planes (s1)
        k_addnorm<<<TTOK, 128, 0, s1>>>(hin, pos, normw, pxnh, pxnl);
        // wait for this layer's weights (converted on s2 during previous layer)
        if (l > 0) cudaStreamWaitEvent(s1, evC[l-1], 0);
        cudaEventRecord(evA[l], s1);
        cudaStreamWaitEvent(s2, evA[l], 0);
        // 2a. in_proj x-half on s1 (cols [0,EINNER)) -> feeds conv
        k_mma<0><<<dim3(EINNER/64, TTOK/64, 1), 128, 0, s1>>>(
            pxnh, pxnl, pwh + OFF_IN + (size_t)l*LIN,
            pwl + OFF_IN + (size_t)l*LIN, pxz,
            DMODEL, DMODEL, DMODEL, 2*EINNER, nullptr, 0);
        // 2b. in_proj z-half on s2 (cols [EINNER,2*EINNER)) -> needed only by scan3
        k_mma<0><<<dim3(EINNER/64, TTOK/64, 1), 128, 0, s2>>>(
            pxnh, pxnl, pwh + OFF_IN + (size_t)l*LIN + (size_t)EINNER*DMODEL,
            pwl + OFF_IN + (size_t)l*LIN + (size_t)EINNER*DMODEL, pxz + EINNER,
            DMODEL, DMODEL, DMODEL, 2*EINNER, nullptr, 0);
        cudaEventRecord(evB[l], s2);
        // convert next layer's weights on s2 (overlaps s1 chain)
        if (l + 1 < NLAYERS) {
            k_cvtw_layer<<<CVT_BLOCKS, 256, 0, s2>>>(inw, xpw, dtw, outw, l+1, pwh, pwl);
            cudaEventRecord(evC[l], s2);
        }
        // 3. conv + SiLU (s1, depends on x-half only)
        k_conv<<<(TTOK*EINNER/4)/256, 256, 0, s1>>>(pxz, convw + (size_t)l*EINNER*4,
                                                    convb + (size_t)l*EINNER, pxi, pxih, pxil);
        // 4. x_proj split-K=8 + reduce -> dbc + planes (s1)
        k_mma<0><<<dim3(1, TTOK/64, 8), 128, 0, s1>>>(
            pxih, pxil, pwh + OFF_XP + (size_t)l*LXP,
            pwl + OFF_XP + (size_t)l*LXP, pdbcp,
            EINNER, EINNER, EINNER, RBC, nullptr, TTOK*RBC);
        k_reduce8<<<(TTOK*RBC)/256, 256, 0, s1>>>(pdbcp, pdbc, pdbch, pdbcl, TTOK*RBC);
        // 5. dt_proj + softplus (s1)
        k_mma<1><<<dim3(EINNER/64, TTOK/64, 1), 128, 0, s1>>>(
            pdbch, pdbcl, pwh + OFF_DT + (size_t)l*LDT,
            pwl + OFF_DT + (size_t)l*LDT, pdt,
            RRANK, RBC, RRANK, EINNER, dtb + (size_t)l*EINNER, 0);
        // 6. scan passes 1-2 (s1, no z dependency)
        k_scan1<<<dim3(EINNER/128, NCHUNK, BATCH), 128, 0, s1>>>(
            pdt, pxi, pdbc, alog + (size_t)l*EINNER*NSTATE, phN, pP, pya, pcum);
        k_scan2<<<(BATCH*EINNER*NSTATE)/256, 256, 0, s1>>>(phN, pP, pS);
        // join z-half before scan3 (gate needs z)
        cudaStreamWaitEvent(s1, evB[l], 0);
        k_scan3<<<dim3(EINNER/128, NCHUNK, BATCH), 128, 0, s1>>>(
            pxi, pdbc, pxz, alog + (size_t)l*EINNER*NSTATE,
            dvec + (size_t)l*EINNER, pS, pya, pcum, pyh, pyl);
        // 7. out_proj split-K=2 -> partials -> reduce -> next h (or final output) (s1)
        float* dest = (l == NLAYERS-1) ? out : ph;
        k_mma<0><<<dim3(DMODEL/64, TTOK/64, 2), 128, 0, s1>>>(
            pyh, pyl, pwh + OFF_OUT + (size_t)l*LOUT,
            pwl + OFF_OUT + (size_t)l*LOUT, pop,
            EINNER, EINNER, EINNER, DMODEL, nullptr, TTOK*DMODEL);
        k_reduce2<<<(TTOK*DMODEL/4)/256, 256, 0, s1>>>(pop, dest, TTOK*DMODEL/4);
    }

    // join back to origin stream
    cudaEventRecord(evJ, s1);
    cudaStreamWaitEvent(0, evJ, 0);
}

// round 16
// speedup vs baseline: 1.0556x; 1.0165x over previous
#include <cuda_runtime.h>
#include <cuda_bf16.h>
#include <math.h>
#include <stdint.h>
#include <cstdint>

// ---------------- problem constants ----------------
#define NLAYERS 6
#define BATCH   2
#define LSEQ    1024
#define DMODEL  512
#define EINNER  1024
#define NSTATE  16
#define RRANK   32
#define RBC     64            // RRANK + 2*NSTATE
#define TTOK    (BATCH*LSEQ)  // 2048
#define NCHUNK  64
#define TCH     (LSEQ/NCHUNK) // 16
#define EPSF    1.1920929e-07f
#define L2E     1.4426950408889634f

// weight plane layout (bf16 hi/lo), element offsets
#define LIN  (2*EINNER*DMODEL)
#define LXP  (RBC*EINNER)
#define LDT  (EINNER*RRANK)
#define LOUT (DMODEL*EINNER)
#define LTOT (LIN+LXP+LDT+LOUT)
#define N_IN   (NLAYERS*LIN)
#define N_XP   (NLAYERS*LXP)
#define N_DT   (NLAYERS*LDT)
#define N_OUT  (NLAYERS*LOUT)
#define OFF_IN  0
#define OFF_XP  (N_IN)
#define OFF_DT  (N_IN+N_XP)
#define OFF_OUT (N_IN+N_XP+N_DT)
#define N_WTOT  (N_IN+N_XP+N_DT+N_OUT)

// ---------------- scratch ----------------
__device__ float g_xz  [TTOK*2*EINNER];
__device__ float g_xi  [TTOK*EINNER];
__device__ float g_dbcp[16*TTOK*RBC];
__device__ float g_dbc [TTOK*RBC];
__device__ float g_dt  [TTOK*EINNER];
__device__ float g_ya  [TTOK*EINNER];
__device__ float g_cum [TTOK*EINNER];
__device__ float g_op  [2*TTOK*DMODEL];   // out_proj split-K partials
__device__ float g_hN  [BATCH*NCHUNK*EINNER*NSTATE];
__device__ float g_P   [BATCH*NCHUNK*EINNER*NSTATE];
__device__ float g_S   [BATCH*NCHUNK*EINNER*NSTATE];
__device__ __nv_bfloat16 g_wh [N_WTOT], g_wl [N_WTOT];
__device__ __nv_bfloat16 g_xnh[TTOK*DMODEL],  g_xnl[TTOK*DMODEL];
__device__ __nv_bfloat16 g_xih[TTOK*EINNER],  g_xil[TTOK*EINNER];
__device__ __nv_bfloat16 g_dbch[TTOK*RBC],    g_dbcl[TTOK*RBC];
__device__ __nv_bfloat16 g_yh [TTOK*EINNER],  g_yl [TTOK*EINNER];

__device__ __forceinline__ void split_bf16(float v, __nv_bfloat16& h, __nv_bfloat16& l) {
    h = __float2bfloat16(v);
    l = __float2bfloat16(v - __bfloat162float(h));
}

__device__ __forceinline__ float fexp2n(float x) {
    x = fmaxf(x, -126.0f);
    float t = x + 12582912.0f;
    int   i = __float_as_int(t) - 0x4B400000;
    float r = x - (t - 12582912.0f);
    float p =          1.3333558e-3f;
    p = fmaf(p, r, 9.6181291e-3f);
    p = fmaf(p, r, 5.5504109e-2f);
    p = fmaf(p, r, 2.4022651e-1f);
    p = fmaf(p, r, 6.9314718e-1f);
    p = fmaf(p, r, 1.0f);
    return __int_as_float(__float_as_int(p) + (i << 23));
}

__device__ __forceinline__ float softplusf(float x) {
    return fmaxf(x, 0.0f) + log1pf(__expf(-fabsf(x)));
}

#define LDSM4(r0,r1,r2,r3,addr) \
    asm volatile("ldmatrix.sync.aligned.m8n8.x4.shared.b16 {%0,%1,%2,%3}, [%4];" \
        : "=r"(r0), "=r"(r1), "=r"(r2), "=r"(r3) : "r"(addr))

#define CP16(dst_u32, src_ptr) \
    asm volatile("cp.async.cg.shared.global [%0], [%1], 16;" :: "r"(dst_u32), "l"(src_ptr))
#define CP_COMMIT() asm volatile("cp.async.commit_group;" ::: "memory")
#define CP_WAIT0()  asm volatile("cp.async.wait_group 0;" ::: "memory")

// ---------------- K0: per-layer weights -> bf16 hi/lo planes ----------------
__global__ void k_cvtw_layer(const float* __restrict__ inw, const float* __restrict__ xpw,
                             const float* __restrict__ dtw, const float* __restrict__ outw,
                             int l,
                             __nv_bfloat16* __restrict__ wh, __nv_bfloat16* __restrict__ wl) {
    int e0 = (blockIdx.x * blockDim.x + threadIdx.x) * 4;
    if (e0 >= LTOT) return;
    const float* src; size_t doff;
    if      (e0 < LIN)          { src = inw  + (size_t)l*LIN + e0;
                                  doff = OFF_IN  + (size_t)l*LIN + e0; }
    else if (e0 < LIN+LXP)      { src = xpw  + (size_t)l*LXP + (e0 - LIN);
                                  doff = OFF_XP  + (size_t)l*LXP + (e0 - LIN); }
    else if (e0 < LIN+LXP+LDT)  { src = dtw  + (size_t)l*LDT + (e0 - LIN - LXP);
                                  doff = OFF_DT  + (size_t)l*LDT + (e0 - LIN - LXP); }
    else                        { src = outw + (size_t)l*LOUT + (e0 - LIN - LXP - LDT);
                                  doff = OFF_OUT + (size_t)l*LOUT + (e0 - LIN - LXP - LDT); }
    float4 v = *(const float4*)src;
    __nv_bfloat16 h0,h1,h2,h3,l0,l1,l2,l3;
    split_bf16(v.x,h0,l0); split_bf16(v.y,h1,l1);
    split_bf16(v.z,h2,l2); split_bf16(v.w,h3,l3);
    *(__nv_bfloat162*)&wh[doff]   = __nv_bfloat162(h0,h1);
    *(__nv_bfloat162*)&wh[doff+2] = __nv_bfloat162(h2,h3);
    *(__nv_bfloat162*)&wl[doff]   = __nv_bfloat162(l0,l1);
    *(__nv_bfloat162*)&wl[doff+2] = __nv_bfloat162(l2,l3);
}

// ---------------- addnorm core ----------------
__device__ __forceinline__ void addnorm_core(float4 v, const float* __restrict__ nw,
                                             __nv_bfloat16* __restrict__ oh,
                                             __nv_bfloat16* __restrict__ ol,
                                             int t, int tid) {
    float ss = v.x*v.x + v.y*v.y + v.z*v.z + v.w*v.w;
    #pragma unroll
    for (int o = 16; o > 0; o >>= 1) ss += __shfl_xor_sync(0xffffffffu, ss, o);
    __shared__ float sred[4];
    if ((tid & 31) == 0) sred[tid >> 5] = ss;
    __syncthreads();
    ss = sred[0] + sred[1] + sred[2] + sred[3];
    float s = rsqrtf(ss * (1.0f/DMODEL) + EPSF);
    float4 w = ((const float4*)nw)[tid];
    float o0 = v.x*s*w.x, o1 = v.y*s*w.y, o2 = v.z*s*w.z, o3 = v.w*s*w.w;
    __nv_bfloat16 h0,h1,h2,h3,l0,l1,l2,l3;
    split_bf16(o0,h0,l0); split_bf16(o1,h1,l1);
    split_bf16(o2,h2,l2); split_bf16(o3,h3,l3);
    int base = t*DMODEL + tid*4;
    *(__nv_bfloat162*)&oh[base]   = __nv_bfloat162(h0,h1);
    *(__nv_bfloat162*)&oh[base+2] = __nv_bfloat162(h2,h3);
    *(__nv_bfloat162*)&ol[base]   = __nv_bfloat162(l0,l1);
    *(__nv_bfloat162*)&ol[base+2] = __nv_bfloat162(l2,l3);
}

// K1a: layer 0 — h from input x
__global__ void k_addnorm(const float* __restrict__ hin, const float* __restrict__ pos,
                          const float* __restrict__ nw,
                          __nv_bfloat16* __restrict__ oh, __nv_bfloat16* __restrict__ ol) {
    int t = blockIdx.x, tid = threadIdx.x;
    float4 v  = ((const float4*)(hin + t*DMODEL))[tid];
    float4 pv = ((const float4*)(pos + t*DMODEL))[tid];
    v.x += pv.x; v.y += pv.y; v.z += pv.z; v.w += pv.w;
    addnorm_core(v, nw, oh, ol, t, tid);
}

// K1b: layers 1..5 — h = out_proj partial0 + partial1 (fused reduce2)
__global__ void k_addnorm2(const float* __restrict__ p0, const float* __restrict__ p1,
                           const float* __restrict__ pos, const float* __restrict__ nw,
                           __nv_bfloat16* __restrict__ oh, __nv_bfloat16* __restrict__ ol) {
    int t = blockIdx.x, tid = threadIdx.x;
    float4 a  = ((const float4*)(p0 + t*DMODEL))[tid];
    float4 b  = ((const float4*)(p1 + t*DMODEL))[tid];
    float4 pv = ((const float4*)(pos + t*DMODEL))[tid];
    float4 v;
    v.x = a.x + b.x + pv.x; v.y = a.y + b.y + pv.y;
    v.z = a.z + b.z + pv.z; v.w = a.w + b.w + pv.w;
    addnorm_core(v, nw, oh, ol, t, tid);
}

// ---------------- bf16-split MMA GEMM (R13 proven: 64x64, 128 thr, 2-stage) ----------
__device__ __forceinline__ void mma_bf16(float (&d)[4], const unsigned (&a)[4],
                                         const unsigned (&b)[2]) {
    asm volatile(
        "mma.sync.aligned.m16n8k16.row.col.f32.bf16.bf16.f32 "
        "{%0,%1,%2,%3}, {%4,%5,%6,%7}, {%8,%9}, {%0,%1,%2,%3};\n"
        : "+f"(d[0]), "+f"(d[1]), "+f"(d[2]), "+f"(d[3])
        : "r"(a[0]), "r"(a[1]), "r"(a[2]), "r"(a[3]), "r"(b[0]), "r"(b[1]));
}

template<int EPI>
__global__ void __launch_bounds__(128)
k_mma(const __nv_bfloat16* __restrict__ Agh, const __nv_bfloat16* __restrict__ Agl,
      const __nv_bfloat16* __restrict__ Bgh, const __nv_bfloat16* __restrict__ Bgl,
      float* __restrict__ C, int K, int lda, int ldw, int ldc,
      const float* __restrict__ bias, int pstride)
{
    constexpr int BM = 64, BK = 32, THREADS = 128;
    constexpr int TM = 2, TN = 4;
    constexpr int LST = BK + 8;
    constexpr int BUFB = BM*LST*2;

    __shared__ __align__(16) __nv_bfloat16 Ah[2][BM*LST], Al[2][BM*LST];
    __shared__ __align__(16) __nv_bfloat16 Bh[2][BM*LST], Bl[2][BM*LST];

    const int tid  = threadIdx.x;
    const int lane = tid & 31;
    const int warp = tid >> 5;
    const int wm = (warp >> 1) * 32;
    const int wn = (warp & 1) * 32;
    const int m0 = blockIdx.y * BM, n0 = blockIdx.x * BM;
    const int kLen = K / gridDim.z;
    const int k0 = blockIdx.z * kLen;
    const int niter = kLen / BK;

    const int laneq = lane & 7;
    const int a_rowoff = (wm + laneq + ((lane>>3)&1)*8) * LST;
    const int a_koff   = (lane>>4)*8;
    const int b_rowoff = (wn + (lane>>4)*8 + laneq) * LST;
    const int b_koff   = ((lane>>3)&1)*8;

    const unsigned uAh = (unsigned)__cvta_generic_to_shared(&Ah[0][0]);
    const unsigned uAl = (unsigned)__cvta_generic_to_shared(&Al[0][0]);
    const unsigned uBh = (unsigned)__cvta_generic_to_shared(&Bh[0][0]);
    const unsigned uBl = (unsigned)__cvta_generic_to_shared(&Bl[0][0]);

    float acc[TM][TN][4];
    #pragma unroll
    for (int i = 0; i < TM; i++)
        #pragma unroll
        for (int j = 0; j < TN; j++)
            #pragma unroll
            for (int q = 0; q < 4; q++) acc[i][j][q] = 0.0f;

    const int r_  = tid >> 2,             kc_  = tid & 3;
    const int r2_ = (tid + THREADS) >> 2, kc2_ = (tid + THREADS) & 3;
    const int o0b = (r_*LST + kc_*8) * 2, o1b = (r2_*LST + kc2_*8) * 2;

    auto issue_tile = [&](int buf, int kb) {
        const int bb = buf * BUFB;
        size_t gA0 = (size_t)(m0 + r_ ) * lda + kb + kc_ *8;
        size_t gA1 = (size_t)(m0 + r2_) * lda + kb + kc2_*8;
        size_t gB0 = (size_t)(n0 + r_ ) * ldw + kb + kc_ *8;
        size_t gB1 = (size_t)(n0 + r2_) * ldw + kb + kc2_*8;
        CP16(uAh + bb + o0b, &Agh[gA0]);
        CP16(uAl + bb + o0b, &Agl[gA0]);
        CP16(uAh + bb + o1b, &Agh[gA1]);
        CP16(uAl + bb + o1b, &Agl[gA1]);
        CP16(uBh + bb + o0b, &Bgh[gB0]);
        CP16(uBl + bb + o0b, &Bgl[gB0]);
        CP16(uBh + bb + o1b, &Bgh[gB1]);
        CP16(uBl + bb + o1b, &Bgl[gB1]);
        CP_COMMIT();
    };

    issue_tile(0, k0);
    CP_WAIT0();
    __syncthreads();

    for (int kt = 0; kt < niter; kt++) {
        const int cur = kt & 1;
        const bool more = (kt + 1 < niter);
        if (more) issue_tile(cur ^ 1, k0 + (kt+1)*BK);

        const int bufB = cur * BUFB;
        #pragma unroll
        for (int s = 0; s < 2; s++) {
            unsigned bhf[TN][2], blf[TN][2];
            {
                int boff = bufB + (b_rowoff + s*16 + b_koff) * 2;
                unsigned t0,t1,t2,t3;
                LDSM4(t0,t1,t2,t3, uBh + boff);
                bhf[0][0]=t0; bhf[0][1]=t1; bhf[1][0]=t2; bhf[1][1]=t3;
                LDSM4(t0,t1,t2,t3, uBh + boff + 16*LST*2);
                bhf[2][0]=t0; bhf[2][1]=t1; bhf[3][0]=t2; bhf[3][1]=t3;
                LDSM4(t0,t1,t2,t3, uBl + boff);
                blf[0][0]=t0; blf[0][1]=t1; blf[1][0]=t2; blf[1][1]=t3;
                LDSM4(t0,t1,t2,t3, uBl + boff + 16*LST*2);
                blf[2][0]=t0; blf[2][1]=t1; blf[3][0]=t2; blf[3][1]=t3;
            }
            #pragma unroll
            for (int i = 0; i < TM; i++) {
                int aoff = bufB + (a_rowoff + i*16*LST + s*16 + a_koff) * 2;
                unsigned ahf[4], alf[4];
                LDSM4(ahf[0],ahf[1],ahf[2],ahf[3], uAh + aoff);
                LDSM4(alf[0],alf[1],alf[2],alf[3], uAl + aoff);
                #pragma unroll
                for (int j = 0; j < TN; j++) {
                    mma_bf16(acc[i][j], ahf, bhf[j]);
                    mma_bf16(acc[i][j], ahf, blf[j]);
                    mma_bf16(acc[i][j], alf, bhf[j]);
                }
            }
        }

        if (more) { CP_WAIT0(); }
        __syncthreads();
    }

    float* Cp = C + (size_t)blockIdx.z * pstride;
    #pragma unroll
    for (int i = 0; i < TM; i++) {
        int row = m0 + wm + i*16 + (lane >> 2);
        #pragma unroll
        for (int j = 0; j < TN; j++) {
            int col = n0 + wn + j*8 + (lane & 3)*2;
            float2 v0, v1;
            if (EPI == 1) {
                float b0 = bias[col], b1 = bias[col+1];
                v0.x = softplusf(acc[i][j][0] + b0);
                v0.y = softplusf(acc[i][j][1] + b1);
                v1.x = softplusf(acc[i][j][2] + b0);
                v1.y = softplusf(acc[i][j][3] + b1);
            } else {
                v0.x = acc[i][j][0]; v0.y = acc[i][j][1];
                v1.x = acc[i][j][2]; v1.y = acc[i][j][3];
            }
            *(float2*)&Cp[(size_t)row * ldc + col]     = v0;
            *(float2*)&Cp[(size_t)(row+8) * ldc + col] = v1;
        }
    }
}

// ---------------- K3: causal depthwise conv (k=4) + bias + SiLU ----------------
__global__ void k_conv(const float* __restrict__ xz, const float* __restrict__ cw,
                       const float* __restrict__ cb, float* __restrict__ xi,
                       __nv_bfloat16* __restrict__ xih, __nv_bfloat16* __restrict__ xil) {
    int idx = blockIdx.x * blockDim.x + threadIdx.x;
    int e  = idx & (EINNER - 1);
    int lg = (idx >> 10) & (LSEQ/4 - 1);
    int b  = idx >> 18;
    int l0 = lg * 4;
    const float* base = xz + (size_t)(b * LSEQ) * 2 * EINNER + e;
    float xv[7];
    #pragma unroll
    for (int j = 0; j < 7; j++) {
        int li = l0 - 3 + j;
        xv[j] = (li >= 0) ? base[(size_t)li * 2 * EINNER] : 0.0f;
    }
    float w0 = cw[e*4+0], w1 = cw[e*4+1], w2 = cw[e*4+2], w3 = cw[e*4+3];
    float bb = cb[e];
    #pragma unroll
    for (int t = 0; t < 4; t++) {
        float acc = bb;
        acc = fmaf(w0, xv[t+0], acc);
        acc = fmaf(w1, xv[t+1], acc);
        acc = fmaf(w2, xv[t+2], acc);
        acc = fmaf(w3, xv[t+3], acc);
        float v = acc / (1.0f + __expf(-acc));
        size_t oi = (size_t)(b*LSEQ + l0 + t) * EINNER + e;
        xi[oi] = v;
        __nv_bfloat16 h, lo; split_bf16(v, h, lo);
        xih[oi] = h; xil[oi] = lo;
    }
}

// ---------------- split-K=16 reduce for x_proj (+ bf16 planes) ----------------
__global__ void k_reduce16(const float* __restrict__ part, float* __restrict__ out,
                           __nv_bfloat16* __restrict__ oh, __nv_bfloat16* __restrict__ ol,
                           int n) {
    int i = blockIdx.x * blockDim.x + threadIdx.x;
    if (i < n) {
        float s = 0.f;
        #pragma unroll
        for (int z = 0; z < 16; z++) s += part[(size_t)z * n + i];
        out[i] = s;
        __nv_bfloat16 h, lo; split_bf16(s, h, lo);
        oh[i] = h; ol[i] = lo;
    }
}

// ---------------- split-K=2 reduce for out_proj (final layer only) ----------------
__global__ void k_reduce2(const float* __restrict__ part, float* __restrict__ out, int n4) {
    int i = blockIdx.x * blockDim.x + threadIdx.x;
    if (i < n4) {
        float4 a = ((const float4*)part)[i];
        float4 b = ((const float4*)(part + (size_t)n4*4))[i];
        a.x += b.x; a.y += b.y; a.z += b.z; a.w += b.w;
        ((float4*)out)[i] = a;
    }
}

// ---------------- A setup helper ----------------
__device__ __forceinline__ bool load_A(const float* __restrict__ Alog, int e,
                                       float (&A2)[NSTATE]) {
    bool st = true;
    float A0 = -__expf(Alog[e*NSTATE]);
    #pragma unroll
    for (int n = 0; n < NSTATE; n++) {
        float An = -__expf(Alog[e*NSTATE + n]);
        A2[n] = An * L2E;
        st = st && (fabsf(An - (n+1)*A0) <= 1e-5f * fabsf(An));
    }
    return st;
}

// ---------------- scan pass 1 ----------------
__global__ void k_scan1(const float* __restrict__ dt, const float* __restrict__ u,
                        const float* __restrict__ dbc, const float* __restrict__ Alog,
                        float* __restrict__ hN, float* __restrict__ P,
                        float* __restrict__ yacc, float* __restrict__ cum) {
    int e = blockIdx.x * 128 + threadIdx.x;
    int c = blockIdx.y, b = blockIdx.z;
    int rowbase = b * LSEQ + c * TCH;
    __shared__ float sBC[TCH][2*NSTATE];
    for (int i = threadIdx.x; i < TCH*2*NSTATE; i += 128) {
        int r = i >> 5, n = i & 31;
        sBC[r][n] = dbc[(size_t)(rowbase + r) * RBC + RRANK + n];
    }
    float A2[NSTATE];
    bool st = load_A(Alog, e, A2);
    __syncthreads();

    float h[NSTATE];
    #pragma unroll
    for (int n = 0; n < NSTATE; n++) h[n] = 0.f;
    float cumd = 0.f;
    for (int tt = 0; tt < TCH; tt++) {
        int row = rowbase + tt;
        float d  = dt[(size_t)row * EINNER + e];
        float uu = u [(size_t)row * EINNER + e];
        float du = d * uu;
        float acc = 0.f;
        if (st) {
            float w = fexp2n(d * A2[0]);
            float a = 1.0f;
            #pragma unroll
            for (int n = 0; n < NSTATE; n++) {
                a *= w;
                h[n] = fmaf(a, h[n], du * sBC[tt][n]);
                acc = fmaf(h[n], sBC[tt][NSTATE + n], acc);
            }
        } else {
            #pragma unroll
            for (int n = 0; n < NSTATE; n++) {
                float a = fexp2n(d * A2[n]);
                h[n] = fmaf(a, h[n], du * sBC[tt][n]);
                acc = fmaf(h[n], sBC[tt][NSTATE + n], acc);
            }
        }
        cumd += d;
        size_t oi = (size_t)row * EINNER + e;
        yacc[oi] = acc;
        cum[oi]  = cumd;
    }
    int o = ((b * NCHUNK + c) * EINNER + e) * NSTATE;
    if (st) {
        float ws = fexp2n(cumd * A2[0]);
        float a = 1.0f;
        #pragma unroll
        for (int n = 0; n < NSTATE; n++) { a *= ws; hN[o+n] = h[n]; P[o+n] = a; }
    } else {
        #pragma unroll
        for (int n = 0; n < NSTATE; n++) { hN[o+n] = h[n]; P[o+n] = fexp2n(cumd * A2[n]); }
    }
}

// ---------------- scan pass 2 ----------------
__global__ void k_scan2(const float* __restrict__ hN, const float* __restrict__ P,
                        float* __restrict__ S) {
    int idx = blockIdx.x * blockDim.x + threadIdx.x;
    int b = idx >> 14;
    int r = idx & 16383;
    float s = 0.f;
    int base = b * NCHUNK * EINNER * NSTATE + r;
    #pragma unroll 8
    for (int c = 0; c < NCHUNK; c++) {
        S[base + c * EINNER * NSTATE] = s;
        s = hN[base + c * EINNER * NSTATE] + P[base + c * EINNER * NSTATE] * s;
    }
}

// ---------------- scan pass 3: parallel correction ----------------
__global__ void k_scan3(const float* __restrict__ u, const float* __restrict__ dbc,
                        const float* __restrict__ xz, const float* __restrict__ Alog,
                        const float* __restrict__ Dv, const float* __restrict__ S,
                        const float* __restrict__ yacc, const float* __restrict__ cum,
                        __nv_bfloat16* __restrict__ yh, __nv_bfloat16* __restrict__ yl) {
    int e = blockIdx.x * 128 + threadIdx.x;
    int c = blockIdx.y, b = blockIdx.z;
    int rowbase = b * LSEQ + c * TCH;
    __shared__ float sC[TCH][NSTATE];
    for (int i = threadIdx.x; i < TCH*NSTATE; i += 128) {
        int r = i >> 4, n = i & 15;
        sC[r][n] = dbc[(size_t)(rowbase + r) * RBC + RRANK + NSTATE + n];
    }
    float A2[NSTATE];
    bool st = load_A(Alog, e, A2);
    float Dd = Dv[e];
    float sreg[NSTATE];
    int o = ((b * NCHUNK + c) * EINNER + e) * NSTATE;
    #pragma unroll
    for (int n = 0; n < NSTATE; n++) sreg[n] = S[o + n];
    __syncthreads();

    for (int tt = 0; tt < TCH; tt++) {
        int row = rowbase + tt;
        size_t oi = (size_t)row * EINNER + e;
        float cd = cum[oi];
        float acc = yacc[oi];
        float uu  = u[oi];
        float zz  = xz[(size_t)row * 2 * EINNER + EINNER + e];
        if (st) {
            float wS = fexp2n(cd * A2[0]);
            float a = 1.0f;
            #pragma unroll
            for (int n = 0; n < NSTATE; n++) {
                a *= wS;
                acc = fmaf(a * sreg[n], sC[tt][n], acc);
            }
        } else {
            #pragma unroll
            for (int n = 0; n < NSTATE; n++)
                acc = fmaf(fexp2n(cd * A2[n]) * sreg[n], sC[tt][n], acc);
        }
        acc = fmaf(uu, Dd, acc);
        float sz = zz / (1.0f + __expf(-zz));
        float yv = acc * sz;
        __nv_bfloat16 hh, ll; split_bf16(yv, hh, ll);
        yh[oi] = hh; yl[oi] = ll;
    }
}

// ---------------- launcher: dual-stream overlap + lazy cvt + fused reduce2 ------
extern "C" void kernel_launch(void* const* d_in, const int* in_sizes, int n_in,
                              void* d_out, int out_size) {
    const float* x     = (const float*)d_in[0];
    const float* pos   = (const float*)d_in[1];
    const float* normw = (const float*)d_in[2];
    const float* inw   = (const float*)d_in[3];
    const float* convw = (const float*)d_in[4];
    const float* convb = (const float*)d_in[5];
    const float* xpw   = (const float*)d_in[6];
    const float* dtw   = (const float*)d_in[7];
    const float* dtb   = (const float*)d_in[8];
    const float* alog  = (const float*)d_in[9];
    const float* dvec  = (const float*)d_in[10];
    const float* outw  = (const float*)d_in[11];
    float* out = (float*)d_out;
    (void)in_sizes; (void)n_in; (void)out_size;

    static cudaStream_t s1, s2;
    static cudaEvent_t ev0, evJ, evA[NLAYERS], evB[NLAYERS], evC[NLAYERS];
    static int inited = 0;
    if (!inited) {
        cudaStreamCreateWithFlags(&s1, cudaStreamNonBlocking);
        cudaStreamCreateWithFlags(&s2, cudaStreamNonBlocking);
        cudaEventCreateWithFlags(&ev0, cudaEventDisableTiming);
        cudaEventCreateWithFlags(&evJ, cudaEventDisableTiming);
        for (int l = 0; l < NLAYERS; l++) {
            cudaEventCreateWithFlags(&evA[l], cudaEventDisableTiming);
            cudaEventCreateWithFlags(&evB[l], cudaEventDisableTiming);
            cudaEventCreateWithFlags(&evC[l], cudaEventDisableTiming);
        }
        inited = 1;
    }

    float *pxz, *pxi, *pdbcp, *pdbc, *pdt, *pya, *pcum, *pop, *phN, *pP, *pS;
    __nv_bfloat16 *pwh, *pwl, *pxnh, *pxnl, *pxih, *pxil, *pdbch, *pdbcl, *pyh, *pyl;
    cudaGetSymbolAddress((void**)&pxz,   g_xz);
    cudaGetSymbolAddress((void**)&pxi,   g_xi);
    cudaGetSymbolAddress((void**)&pdbcp, g_dbcp);
    cudaGetSymbolAddress((void**)&pdbc,  g_dbc);
    cudaGetSymbolAddress((void**)&pdt,   g_dt);
    cudaGetSymbolAddress((void**)&pya,   g_ya);
    cudaGetSymbolAddress((void**)&pcum,  g_cum);
    cudaGetSymbolAddress((void**)&pop,   g_op);
    cudaGetSymbolAddress((void**)&phN,   g_hN);
    cudaGetSymbolAddress((void**)&pP,    g_P);
    cudaGetSymbolAddress((void**)&pS,    g_S);
    cudaGetSymbolAddress((void**)&pwh,   g_wh);
    cudaGetSymbolAddress((void**)&pwl,   g_wl);
    cudaGetSymbolAddress((void**)&pxnh,  g_xnh);
    cudaGetSymbolAddress((void**)&pxnl,  g_xnl);
    cudaGetSymbolAddress((void**)&pxih,  g_xih);
    cudaGetSymbolAddress((void**)&pxil,  g_xil);
    cudaGetSymbolAddress((void**)&pdbch, g_dbch);
    cudaGetSymbolAddress((void**)&pdbcl, g_dbcl);
    cudaGetSymbolAddress((void**)&pyh,   g_yh);
    cudaGetSymbolAddress((void**)&pyl,   g_yl);

    const int CVT_BLOCKS = (LTOT/4 + 255) / 256;

    // fork from the origin (default) stream
    cudaEventRecord(ev0, 0);
    cudaStreamWaitEvent(s1, ev0, 0);
    cudaStreamWaitEvent(s2, ev0, 0);

    // layer 0 weights converted up-front on s1
    k_cvtw_layer<<<CVT_BLOCKS, 256, 0, s1>>>(inw, xpw, dtw, outw, 0, pwh, pwl);

    for (int l = 0; l < NLAYERS; l++) {
        // 1. h (+pos) -> rmsnorm -> xn planes (s1); layers >0 fuse out_proj partial sum
        if (l == 0)
            k_addnorm<<<TTOK, 128, 0, s1>>>(x, pos, normw, pxnh, pxnl);
        else
            k_addnorm2<<<TTOK, 128, 0, s1>>>(pop, pop + (size_t)TTOK*DMODEL, pos, normw,
                                             pxnh, pxnl);
        // wait for this layer's weights (converted on s2 during previous layer)
        if (l > 0) cudaStreamWaitEvent(s1, evC[l-1], 0);
        cudaEventRecord(evA[l], s1);
        cudaStreamWaitEvent(s2, evA[l], 0);
        // 2a. in_proj x-half on s1 (cols [0,EINNER)) -> feeds conv
        k_mma<0><<<dim3(EINNER/64, TTOK/64, 1), 128, 0, s1>>>(
            pxnh, pxnl, pwh + OFF_IN + (size_t)l*LIN,
            pwl + OFF_IN + (size_t)l*LIN, pxz,
            DMODEL, DMODEL, DMODEL, 2*EINNER, nullptr, 0);
        // 2b. in_proj z-half on s2 (cols [EINNER,2*EINNER)) -> needed only by scan3
        k_mma<0><<<dim3(EINNER/64, TTOK/64, 1), 128, 0, s2>>>(
            pxnh, pxnl, pwh + OFF_IN + (size_t)l*LIN + (size_t)EINNER*DMODEL,
            pwl + OFF_IN + (size_t)l*LIN + (size_t)EINNER*DMODEL, pxz + EINNER,
            DMODEL, DMODEL, DMODEL, 2*EINNER, nullptr, 0);
        cudaEventRecord(evB[l], s2);
        // convert next layer's weights on s2 (overlaps s1 chain)
        if (l + 1 < NLAYERS) {
            k_cvtw_layer<<<CVT_BLOCKS, 256, 0, s2>>>(inw, xpw, dtw, outw, l+1, pwh, pwl);
            cudaEventRecord(evC[l], s2);
        }
        // 3. conv + SiLU (s1, depends on x-half only)
        k_conv<<<(TTOK*EINNER/4)/256, 256, 0, s1>>>(pxz, convw + (size_t)l*EINNER*4,
                                                    convb + (size_t)l*EINNER, pxi, pxih, pxil);
        // 4. x_proj split-K=16 + reduce -> dbc + planes (s1)
        k_mma<0><<<dim3(1, TTOK/64, 16), 128, 0, s1>>>(
            pxih, pxil, pwh + OFF_XP + (size_t)l*LXP,
            pwl + OFF_XP + (size_t)l*LXP, pdbcp,
            EINNER, EINNER, EINNER, RBC, nullptr, TTOK*RBC);
        k_reduce16<<<(TTOK*RBC)/256, 256, 0, s1>>>(pdbcp, pdbc, pdbch, pdbcl, TTOK*RBC);
        // 5. dt_proj + softplus (s1)
        k_mma<1><<<dim3(EINNER/64, TTOK/64, 1), 128, 0, s1>>>(
            pdbch, pdbcl, pwh + OFF_DT + (size_t)l*LDT,
            pwl + OFF_DT + (size_t)l*LDT, pdt,
            RRANK, RBC, RRANK, EINNER, dtb + (size_t)l*EINNER, 0);
        // 6. scan passes 1-2 (s1, no z dependency)
        k_scan1<<<dim3(EINNER/128, NCHUNK, BATCH), 128, 0, s1>>>(
            pdt, pxi, pdbc, alog + (size_t)l*EINNER*NSTATE, phN, pP, pya, pcum);
        k_scan2<<<(BATCH*EINNER*NSTATE)/256, 256, 0, s1>>>(phN, pP, pS);
        // join z-half before scan3 (gate needs z)
        cudaStreamWaitEvent(s1, evB[l], 0);
        k_scan3<<<dim3(EINNER/128, NCHUNK, BATCH), 128, 0, s1>>>(
            pxi, pdbc, pxz, alog + (size_t)l*EINNER*NSTATE,
            dvec + (size_t)l*EINNER, pS, pya, pcum, pyh, pyl);
        // 7. out_proj split-K=2 -> partials (s1); reduce fused into next addnorm
        k_mma<0><<<dim3(DMODEL/64, TTOK/64, 2), 128, 0, s1>>>(
            pyh, pyl, pwh + OFF_OUT + (size_t)l*LOUT,
            pwl + OFF_OUT + (size_t)l*LOUT, pop,
            EINNER, EINNER, EINNER, DMODEL, nullptr, TTOK*DMODEL);
        if (l == NLAYERS-1)
            k_reduce2<<<(TTOK*DMODEL/4)/256, 256, 0, s1>>>(pop, out, TTOK*DMODEL/4);
    }

    // join back to origin stream
    cudaEventRecord(evJ, s1);
    cudaStreamWaitEvent(0, evJ, 0);
}